// round 4
// baseline (speedup 1.0000x reference)
#include <cuda_runtime.h>

// Problem constants
constexpr int NB = 16;
constexpr int NC = 128;
constexpr int NH = 64;
constexpr int NW = 64;
constexpr int HW = NH * NW;
constexpr int NOC = 128;

// Scratch (allocation-free rule: __device__ globals)
__device__ float g_T[NB * 2 * HW];     // per-parity channel sums
__device__ float g_avg[NB * 2 * HW];   // 3x3 box mean / 576
__device__ float g_W2[NOC * 2];        // sum of weights per (o, parity)

// ---------------------------------------------------------------------------
// Kernel 1: per-pixel channel-parity sums  T[b,u,y,x] = sum_{c%2==u} x[b,c,y,x]
// ---------------------------------------------------------------------------
__global__ void parity_sum_kernel(const float* __restrict__ x) {
    int idx = blockIdx.x * blockDim.x + threadIdx.x;  // b*HW + pix
    if (idx >= NB * HW) return;
    int b = idx / HW;
    int pix = idx - b * HW;
    const float* xp = x + (size_t)b * NC * HW + pix;
    float s0 = 0.f, s1 = 0.f;
#pragma unroll 8
    for (int c = 0; c < NC; c += 2) {
        s0 += xp[(size_t)c * HW];
        s1 += xp[(size_t)(c + 1) * HW];
    }
    g_T[(b * 2 + 0) * HW + pix] = s0;
    g_T[(b * 2 + 1) * HW + pix] = s1;
}

// ---------------------------------------------------------------------------
// Kernel 2: 3x3 edge-clamped box filter / 576 -> g_avg
// ---------------------------------------------------------------------------
__global__ void avg_kernel() {
    int idx = blockIdx.x * blockDim.x + threadIdx.x;  // (b*2+u)*HW + pix
    if (idx >= NB * 2 * HW) return;
    int bu = idx / HW;
    int pix = idx - bu * HW;
    int i = pix / NW, j = pix - (pix / NW) * NW;
    const float* T = g_T + bu * HW;
    float s = 0.f;
#pragma unroll
    for (int r = -1; r <= 1; r++) {
        int y = min(max(i + r, 0), NH - 1);
#pragma unroll
        for (int q = -1; q <= 1; q++) {
            int xw = min(max(j + q, 0), NW - 1);
            s += T[y * NW + xw];
        }
    }
    g_avg[idx] = s * (1.0f / 576.0f);
}

// ---------------------------------------------------------------------------
// Kernel 3: W2[o,u] = sum_{c%2==u} sum_{r,s} w[o,c,r,s]
// ---------------------------------------------------------------------------
__global__ void w2_kernel(const float* __restrict__ w) {
    int t = threadIdx.x;  // 0..255 -> (o, u)
    if (t >= NOC * 2) return;
    int o = t >> 1, u = t & 1;
    float s = 0.f;
    for (int c = u; c < NC; c += 2) {
        const float* wp = w + ((size_t)o * NC + c) * 9;
#pragma unroll
        for (int k = 0; k < 9; k++) s += wp[k];
    }
    g_W2[t] = s;
}

// ---------------------------------------------------------------------------
// Kernel 4: fused conv (transposed spatial taps) + bias + mean-correction +
//           LeakyReLU + parity-mean add.
// Block: 32(x) x 16(y) spatial tile, 32 output channels, one batch.
// Thread: 8 oc x (2x in x, 4 in y) = 64 accumulators.
// ---------------------------------------------------------------------------
constexpr int TX = 32;
constexpr int TY = 16;
constexpr int OCT = 32;

__global__ __launch_bounds__(256, 2) void conv_kernel(
    const float* __restrict__ x, const float* __restrict__ w,
    const float* __restrict__ bias, float* __restrict__ out) {
    __shared__ float s_x[TY + 2][TX + 4];   // 18 x 36 (34 used)
    __shared__ float s_w[9][OCT];
    __shared__ float s_bias[OCT];
    __shared__ float s_w2[OCT][2];

    int b = blockIdx.z;
    int ocb = blockIdx.y * OCT;
    int tileX = (blockIdx.x & 1) * TX;         // 2 tiles in x
    int tileY = (blockIdx.x >> 1) * TY;        // 4 tiles in y

    int t = threadIdx.x;
    int tx = t & 15;         // 0..15 -> 2 px each in x
    int ty = (t >> 4) & 3;   // 0..3  -> 4 px each in y
    int oz = t >> 6;         // 0..3  -> 8 oc each

    if (t < OCT) s_bias[t] = bias[ocb + t];
    if (t < OCT * 2) s_w2[t >> 1][t & 1] = g_W2[(ocb + (t >> 1)) * 2 + (t & 1)];

    float acc[8][8];
#pragma unroll
    for (int a = 0; a < 8; a++)
#pragma unroll
        for (int p = 0; p < 8; p++) acc[a][p] = 0.f;

    const float* xb = x + (size_t)b * NC * HW;

    for (int c = 0; c < NC; c++) {
        __syncthreads();
        // load padded 18x34 input tile for channel c (edge clamp)
        for (int l = t; l < 18 * 34; l += 256) {
            int ly = l / 34, lx = l - ly * 34;
            int gy = min(max(tileY - 1 + ly, 0), NH - 1);
            int gx = min(max(tileX - 1 + lx, 0), NW - 1);
            s_x[ly][lx] = xb[(size_t)c * HW + gy * NW + gx];
        }
        // load 32 oc x 9 weights for channel c
        for (int l = t; l < OCT * 9; l += 256) {
            int o = l / 9, k = l - o * 9;
            s_w[k][o] = w[((size_t)(ocb + o) * NC + c) * 9 + k];
        }
        __syncthreads();

        // taps: weight w[o,c,r,s] pairs with input offset (row += s, col += r)
#pragma unroll
        for (int r = 0; r < 3; r++) {
#pragma unroll
            for (int s = 0; s < 3; s++) {
                float xv[8];
#pragma unroll
                for (int yy = 0; yy < 4; yy++)
#pragma unroll
                    for (int xx = 0; xx < 2; xx++)
                        xv[yy * 2 + xx] = s_x[ty * 4 + yy + s][tx * 2 + xx + r];
#pragma unroll
                for (int a = 0; a < 8; a++) {
                    float wv = s_w[r * 3 + s][oz * 8 + a];
#pragma unroll
                    for (int p = 0; p < 8; p++) acc[a][p] += wv * xv[p];
                }
            }
        }
    }

    // epilogue
    const float* avg0 = g_avg + (b * 2 + 0) * HW;
    const float* avg1 = g_avg + (b * 2 + 1) * HW;
#pragma unroll
    for (int yy = 0; yy < 4; yy++) {
        int i = tileY + ty * 4 + yy;
#pragma unroll
        for (int xx = 0; xx < 2; xx++) {
            int j = tileX + tx * 2 + xx;
            float a0 = avg0[i * NW + j];
            float a1 = avg1[i * NW + j];
#pragma unroll
            for (int a = 0; a < 8; a++) {
                int o = ocb + oz * 8 + a;
                float v = acc[a][yy * 2 + xx] + s_bias[oz * 8 + a]
                          - s_w2[oz * 8 + a][0] * a0 - s_w2[oz * 8 + a][1] * a1;
                v = v > 0.f ? v : 0.01f * v;
                v += (o & 1) ? a1 : a0;
                out[((size_t)b * NOC + o) * HW + i * NW + j] = v;
            }
        }
    }
}

// ---------------------------------------------------------------------------
extern "C" void kernel_launch(void* const* d_in, const int* in_sizes, int n_in,
                              void* d_out, int out_size) {
    const float* x = (const float*)d_in[0];     // (16,128,64,64)
    const float* w = (const float*)d_in[1];     // (128,128,3,3)
    const float* bias = (const float*)d_in[2];  // (128,)
    float* out = (float*)d_out;                 // (16,128,64,64)

    parity_sum_kernel<<<(NB * HW + 255) / 256, 256>>>(x);
    avg_kernel<<<(NB * 2 * HW + 255) / 256, 256>>>();
    w2_kernel<<<1, 256>>>(w);

    dim3 grid(8, NOC / OCT, NB);  // 8 spatial tiles x 4 oc-groups x 16 batches
    conv_kernel<<<grid, 256>>>(x, w, bias, out);
}

// round 5
// speedup vs baseline: 1.0007x; 1.0007x over previous
#include <cuda_runtime.h>

// Problem constants
constexpr int NB = 16;
constexpr int NC = 128;
constexpr int NH = 64;
constexpr int NW = 64;
constexpr int HW = NH * NW;
constexpr int NOC = 128;

// Scratch (allocation-free rule: __device__ globals)
__device__ float g_T[NB * 2 * HW];     // per-parity channel sums
__device__ float g_avg[NB * 2 * HW];   // 3x3 box mean / 576
__device__ float g_W2[NOC * 2];        // sum of weights per (o, parity)

// ---------------------------------------------------------------------------
// Kernel 1: per-pixel channel-parity sums  T[b,u,y,x] = sum_{c%2==u} x[b,c,y,x]
// ---------------------------------------------------------------------------
__global__ void parity_sum_kernel(const float* __restrict__ x) {
    int idx = blockIdx.x * blockDim.x + threadIdx.x;  // b*HW + pix
    if (idx >= NB * HW) return;
    int b = idx / HW;
    int pix = idx - b * HW;
    const float* xp = x + (size_t)b * NC * HW + pix;
    float s0 = 0.f, s1 = 0.f;
#pragma unroll 8
    for (int c = 0; c < NC; c += 2) {
        s0 += xp[(size_t)c * HW];
        s1 += xp[(size_t)(c + 1) * HW];
    }
    g_T[(b * 2 + 0) * HW + pix] = s0;
    g_T[(b * 2 + 1) * HW + pix] = s1;
}

// ---------------------------------------------------------------------------
// Kernel 2: 3x3 edge-clamped box filter / 576 -> g_avg
// ---------------------------------------------------------------------------
__global__ void avg_kernel() {
    int idx = blockIdx.x * blockDim.x + threadIdx.x;  // (b*2+u)*HW + pix
    if (idx >= NB * 2 * HW) return;
    int bu = idx / HW;
    int pix = idx - bu * HW;
    int i = pix / NW, j = pix - (pix / NW) * NW;
    const float* T = g_T + bu * HW;
    float s = 0.f;
#pragma unroll
    for (int r = -1; r <= 1; r++) {
        int y = min(max(i + r, 0), NH - 1);
#pragma unroll
        for (int q = -1; q <= 1; q++) {
            int xw = min(max(j + q, 0), NW - 1);
            s += T[y * NW + xw];
        }
    }
    g_avg[idx] = s * (1.0f / 576.0f);
}

// ---------------------------------------------------------------------------
// Kernel 3: W2[o,u] = sum_{c%2==u} sum_{r,s} w[o,c,r,s]
// ---------------------------------------------------------------------------
__global__ void w2_kernel(const float* __restrict__ w) {
    int t = threadIdx.x;  // 0..255 -> (o, u)
    if (t >= NOC * 2) return;
    int o = t >> 1, u = t & 1;
    float s = 0.f;
    for (int c = u; c < NC; c += 2) {
        const float* wp = w + ((size_t)o * NC + c) * 9;
#pragma unroll
        for (int k = 0; k < 9; k++) s += wp[k];
    }
    g_W2[t] = s;
}

// ---------------------------------------------------------------------------
// Kernel 4: fused conv (transposed spatial taps) + bias + mean-correction +
//           LeakyReLU + parity-mean add.
// Block: 32(x) x 16(y) spatial tile, 32 output channels, one batch.
// Thread: 8 oc x (2x in x, 4 in y) = 64 accumulators.
// ---------------------------------------------------------------------------
constexpr int TX = 32;
constexpr int TY = 16;
constexpr int OCT = 32;

__global__ __launch_bounds__(256, 2) void conv_kernel(
    const float* __restrict__ x, const float* __restrict__ w,
    const float* __restrict__ bias, float* __restrict__ out) {
    __shared__ float s_x[TY + 2][TX + 4];   // 18 x 36 (34 used)
    __shared__ float s_w[9][OCT];
    __shared__ float s_bias[OCT];
    __shared__ float s_w2[OCT][2];

    int b = blockIdx.z;
    int ocb = blockIdx.y * OCT;
    int tileX = (blockIdx.x & 1) * TX;         // 2 tiles in x
    int tileY = (blockIdx.x >> 1) * TY;        // 4 tiles in y

    int t = threadIdx.x;
    int tx = t & 15;         // 0..15 -> 2 px each in x
    int ty = (t >> 4) & 3;   // 0..3  -> 4 px each in y
    int oz = t >> 6;         // 0..3  -> 8 oc each

    if (t < OCT) s_bias[t] = bias[ocb + t];
    if (t < OCT * 2) s_w2[t >> 1][t & 1] = g_W2[(ocb + (t >> 1)) * 2 + (t & 1)];

    float acc[8][8];
#pragma unroll
    for (int a = 0; a < 8; a++)
#pragma unroll
        for (int p = 0; p < 8; p++) acc[a][p] = 0.f;

    const float* xb = x + (size_t)b * NC * HW;

    for (int c = 0; c < NC; c++) {
        __syncthreads();
        // load padded 18x34 input tile for channel c (edge clamp)
        for (int l = t; l < 18 * 34; l += 256) {
            int ly = l / 34, lx = l - ly * 34;
            int gy = min(max(tileY - 1 + ly, 0), NH - 1);
            int gx = min(max(tileX - 1 + lx, 0), NW - 1);
            s_x[ly][lx] = xb[(size_t)c * HW + gy * NW + gx];
        }
        // load 32 oc x 9 weights for channel c
        for (int l = t; l < OCT * 9; l += 256) {
            int o = l / 9, k = l - o * 9;
            s_w[k][o] = w[((size_t)(ocb + o) * NC + c) * 9 + k];
        }
        __syncthreads();

        // taps: weight w[o,c,r,s] pairs with input offset (row += s, col += r)
#pragma unroll
        for (int r = 0; r < 3; r++) {
#pragma unroll
            for (int s = 0; s < 3; s++) {
                float xv[8];
#pragma unroll
                for (int yy = 0; yy < 4; yy++)
#pragma unroll
                    for (int xx = 0; xx < 2; xx++)
                        xv[yy * 2 + xx] = s_x[ty * 4 + yy + s][tx * 2 + xx + r];
#pragma unroll
                for (int a = 0; a < 8; a++) {
                    float wv = s_w[r * 3 + s][oz * 8 + a];
#pragma unroll
                    for (int p = 0; p < 8; p++) acc[a][p] += wv * xv[p];
                }
            }
        }
    }

    // epilogue
    const float* avg0 = g_avg + (b * 2 + 0) * HW;
    const float* avg1 = g_avg + (b * 2 + 1) * HW;
#pragma unroll
    for (int yy = 0; yy < 4; yy++) {
        int i = tileY + ty * 4 + yy;
#pragma unroll
        for (int xx = 0; xx < 2; xx++) {
            int j = tileX + tx * 2 + xx;
            float a0 = avg0[i * NW + j];
            float a1 = avg1[i * NW + j];
#pragma unroll
            for (int a = 0; a < 8; a++) {
                int o = ocb + oz * 8 + a;
                float v = acc[a][yy * 2 + xx] + s_bias[oz * 8 + a]
                          - s_w2[oz * 8 + a][0] * a0 - s_w2[oz * 8 + a][1] * a1;
                v = v > 0.f ? v : 0.01f * v;
                v += (o & 1) ? a1 : a0;
                out[((size_t)b * NOC + o) * HW + i * NW + j] = v;
            }
        }
    }
}

// ---------------------------------------------------------------------------
extern "C" void kernel_launch(void* const* d_in, const int* in_sizes, int n_in,
                              void* d_out, int out_size) {
    const float* x = (const float*)d_in[0];     // (16,128,64,64)
    const float* w = (const float*)d_in[1];     // (128,128,3,3)
    const float* bias = (const float*)d_in[2];  // (128,)
    float* out = (float*)d_out;                 // (16,128,64,64)

    parity_sum_kernel<<<(NB * HW + 255) / 256, 256>>>(x);
    avg_kernel<<<(NB * 2 * HW + 255) / 256, 256>>>();
    w2_kernel<<<1, 256>>>(w);

    dim3 grid(8, NOC / OCT, NB);  // 8 spatial tiles x 4 oc-groups x 16 batches
    conv_kernel<<<grid, 256>>>(x, w, bias, out);
}

// round 6
// speedup vs baseline: 1.3087x; 1.3079x over previous
#include <cuda_runtime.h>
#include <cstdint>

// Problem constants
constexpr int NB = 16;
constexpr int NC = 128;
constexpr int NH = 64;
constexpr int NW = 64;
constexpr int HW = NH * NW;
constexpr int NOC = 128;

// Scratch (allocation-free rule: __device__ globals)
__device__ float g_T[NB * 2 * HW];     // per-parity channel sums
__device__ float g_avg[NB * 2 * HW];   // 3x3 box mean / 576
__device__ float g_W2[NOC * 2];        // sum of weights per (o, parity)

// ---------------------------------------------------------------------------
// cp.async helpers
// ---------------------------------------------------------------------------
__device__ __forceinline__ void cp_async4(void* smem_ptr, const void* gmem_ptr) {
    uint32_t s = (uint32_t)__cvta_generic_to_shared(smem_ptr);
    asm volatile("cp.async.ca.shared.global [%0], [%1], 4;" :: "r"(s), "l"(gmem_ptr));
}
__device__ __forceinline__ void cp_commit() {
    asm volatile("cp.async.commit_group;");
}
template <int N>
__device__ __forceinline__ void cp_wait() {
    asm volatile("cp.async.wait_group %0;" :: "n"(N));
}

// ---------------------------------------------------------------------------
// Kernel 1: per-pixel channel-parity sums  T[b,u,y,x] = sum_{c%2==u} x[b,c,y,x]
// ---------------------------------------------------------------------------
__global__ void parity_sum_kernel(const float* __restrict__ x) {
    int idx = blockIdx.x * blockDim.x + threadIdx.x;  // b*HW + pix
    if (idx >= NB * HW) return;
    int b = idx / HW;
    int pix = idx - b * HW;
    const float* xp = x + (size_t)b * NC * HW + pix;
    float s0 = 0.f, s1 = 0.f;
#pragma unroll 8
    for (int c = 0; c < NC; c += 2) {
        s0 += xp[(size_t)c * HW];
        s1 += xp[(size_t)(c + 1) * HW];
    }
    g_T[(b * 2 + 0) * HW + pix] = s0;
    g_T[(b * 2 + 1) * HW + pix] = s1;
}

// ---------------------------------------------------------------------------
// Kernel 2: 3x3 edge-clamped box filter / 576 -> g_avg
// ---------------------------------------------------------------------------
__global__ void avg_kernel() {
    int idx = blockIdx.x * blockDim.x + threadIdx.x;  // (b*2+u)*HW + pix
    if (idx >= NB * 2 * HW) return;
    int bu = idx / HW;
    int pix = idx - bu * HW;
    int i = pix / NW, j = pix - (pix / NW) * NW;
    const float* T = g_T + bu * HW;
    float s = 0.f;
#pragma unroll
    for (int r = -1; r <= 1; r++) {
        int y = min(max(i + r, 0), NH - 1);
#pragma unroll
        for (int q = -1; q <= 1; q++) {
            int xw = min(max(j + q, 0), NW - 1);
            s += T[y * NW + xw];
        }
    }
    g_avg[idx] = s * (1.0f / 576.0f);
}

// ---------------------------------------------------------------------------
// Kernel 3: W2[o,u] = sum_{c%2==u} sum_{r,s} w[o,c,r,s]
// ---------------------------------------------------------------------------
__global__ void w2_kernel(const float* __restrict__ w) {
    int t = threadIdx.x;  // 0..255 -> (o, u)
    if (t >= NOC * 2) return;
    int o = t >> 1, u = t & 1;
    float s = 0.f;
    for (int c = u; c < NC; c += 2) {
        const float* wp = w + ((size_t)o * NC + c) * 9;
#pragma unroll
        for (int k = 0; k < 9; k++) s += wp[k];
    }
    g_W2[t] = s;
}

// ---------------------------------------------------------------------------
// Kernel 4: fused conv (transposed spatial taps) + bias + mean-correction +
//           LeakyReLU + parity-mean add.
// Block: 32(x) x 16(y) spatial tile, 32 output channels, one batch.
// Thread: 8 oc x (2 in x [stride 16], 4 in y) = 64 accumulators.
// Double-buffered cp.async prefetch over channels.
// ---------------------------------------------------------------------------
constexpr int TX = 32;
constexpr int TY = 16;
constexpr int OCT = 32;

__global__ __launch_bounds__(256, 2) void conv_kernel(
    const float* __restrict__ x, const float* __restrict__ w,
    const float* __restrict__ bias, float* __restrict__ out) {
    __shared__ float s_x[2][TY + 2][TX + 4];   // 2 x 18 x 36 (34 used)
    __shared__ float s_w[2][9][OCT];
    __shared__ float s_bias[OCT];
    __shared__ float s_w2[OCT][2];

    int b = blockIdx.z;
    int ocb = blockIdx.y * OCT;
    int tileX = (blockIdx.x & 1) * TX;         // 2 tiles in x
    int tileY = (blockIdx.x >> 1) * TY;        // 4 tiles in y

    int t = threadIdx.x;
    int tx = t & 15;         // 0..15
    int ty = (t >> 4) & 3;   // 0..3  -> 4 px each in y
    int oz = t >> 6;         // 0..3  -> 8 oc each

    if (t < OCT) s_bias[t] = bias[ocb + t];
    if (t < OCT * 2) s_w2[t >> 1][t & 1] = g_W2[(ocb + (t >> 1)) * 2 + (t & 1)];

    float acc[8][8];
#pragma unroll
    for (int a = 0; a < 8; a++)
#pragma unroll
        for (int p = 0; p < 8; p++) acc[a][p] = 0.f;

    const float* xb = x + (size_t)b * NC * HW;

    // async load of one channel (x tile + weights) into buffer `buf`
    auto load_ch = [&](int c, int buf) {
#pragma unroll
        for (int l = t; l < 18 * 34; l += 256) {
            int ly = l / 34, lx = l - ly * 34;
            int gy = min(max(tileY - 1 + ly, 0), NH - 1);
            int gx = min(max(tileX - 1 + lx, 0), NW - 1);
            cp_async4(&s_x[buf][ly][lx], &xb[(size_t)c * HW + gy * NW + gx]);
        }
#pragma unroll
        for (int l = t; l < OCT * 9; l += 256) {
            int o = l / 9, k = l - o * 9;
            cp_async4(&s_w[buf][k][o], &w[((size_t)(ocb + o) * NC + c) * 9 + k]);
        }
    };

    load_ch(0, 0);
    cp_commit();

    for (int c = 0; c < NC; c++) {
        int buf = c & 1;
        if (c + 1 < NC) {
            load_ch(c + 1, buf ^ 1);   // prefetch next channel
            cp_commit();
            cp_wait<1>();              // buffer `buf` (older group) complete
        } else {
            cp_wait<0>();
        }
        __syncthreads();               // buffer `buf` visible to all threads

        // taps: weight w[o,c,r,s] pairs with input offset (row += s, col += r)
#pragma unroll
        for (int r = 0; r < 3; r++) {
#pragma unroll
            for (int s = 0; s < 3; s++) {
                float xv[8];
#pragma unroll
                for (int yy = 0; yy < 4; yy++)
#pragma unroll
                    for (int xx = 0; xx < 2; xx++)
                        xv[yy * 2 + xx] = s_x[buf][ty * 4 + yy + s][tx + 16 * xx + r];
#pragma unroll
                for (int a = 0; a < 8; a++) {
                    float wv = s_w[buf][r * 3 + s][oz * 8 + a];
#pragma unroll
                    for (int p = 0; p < 8; p++) acc[a][p] += wv * xv[p];
                }
            }
        }
        __syncthreads();               // all reads of `buf` done before c+1 overwrites it
    }

    // epilogue
    const float* avg0 = g_avg + (b * 2 + 0) * HW;
    const float* avg1 = g_avg + (b * 2 + 1) * HW;
#pragma unroll
    for (int yy = 0; yy < 4; yy++) {
        int i = tileY + ty * 4 + yy;
#pragma unroll
        for (int xx = 0; xx < 2; xx++) {
            int j = tileX + tx + 16 * xx;
            float a0 = avg0[i * NW + j];
            float a1 = avg1[i * NW + j];
#pragma unroll
            for (int a = 0; a < 8; a++) {
                int o = ocb + oz * 8 + a;
                float v = acc[a][yy * 2 + xx] + s_bias[oz * 8 + a]
                          - s_w2[oz * 8 + a][0] * a0 - s_w2[oz * 8 + a][1] * a1;
                v = v > 0.f ? v : 0.01f * v;
                v += (o & 1) ? a1 : a0;
                out[((size_t)b * NOC + o) * HW + i * NW + j] = v;
            }
        }
    }
}

// ---------------------------------------------------------------------------
extern "C" void kernel_launch(void* const* d_in, const int* in_sizes, int n_in,
                              void* d_out, int out_size) {
    const float* x = (const float*)d_in[0];     // (16,128,64,64)
    const float* w = (const float*)d_in[1];     // (128,128,3,3)
    const float* bias = (const float*)d_in[2];  // (128,)
    float* out = (float*)d_out;                 // (16,128,64,64)

    parity_sum_kernel<<<(NB * HW + 255) / 256, 256>>>(x);
    avg_kernel<<<(NB * 2 * HW + 255) / 256, 256>>>();
    w2_kernel<<<1, 256>>>(w);

    dim3 grid(8, NOC / OCT, NB);  // 8 spatial tiles x 4 oc-groups x 16 batches
    conv_kernel<<<grid, 256>>>(x, w, bias, out);
}